// round 15
// baseline (speedup 1.0000x reference)
#include <cuda_runtime.h>
#include <cuda_bf16.h>
#include <cuda_fp16.h>
#include <cstring>

#define N_NODES   50000
#define N_EDGES   800000
#define DIM       128
#define NUM_GRAPHS 64
#define NUM_CLASSES 3
#define TOT_ENTRIES (N_EDGES + N_NODES)
#define CSPLIT 64
#define CK ((N_NODES + CSPLIT - 1) / CSPLIT)   // 782

// ---------------- scratch (device globals; sanctioned, no allocation) ----------------
__device__ int   v9_is64;
__device__ int   v9_deg[N_NODES];
__device__ float v9_dinv[N_NODES];
__device__ int   v9_rowptr[N_NODES + 1];
__device__ int   v9_cursor[N_NODES];
__device__ __align__(8)  int2  v9_edge[TOT_ENTRIES];   // (src, dinv[src] bits)
__device__ __align__(16) __half v15_T[N_NODES * DIM];  // fp16 gathered buffer
__device__ __align__(16) float v9_hA[N_NODES * DIM];
__device__ __align__(16) float v9_hB[N_NODES * DIM];
__device__ __align__(16) float v14_C[N_NODES * NUM_GRAPHS];        // c[s][g]
__device__ __align__(16) float v14_partial[CSPLIT * NUM_GRAPHS * DIM];
__device__ __align__(16) float v9_pooled2[NUM_GRAPHS * DIM];       // mean(z)*W3 + b3
__device__ int   v9_cnt[NUM_GRAPHS];
__device__ __align__(16) float v9_hid[NUM_GRAPHS * DIM];

__device__ __forceinline__ int ld_idx(const int* p, int i) {
    return v9_is64 ? p[2 * i] : p[i];
}

__device__ __forceinline__ unsigned pk_bf2(float x, float y) {
    __nv_bfloat162 h = __floats2bfloat162_rn(x, y);
    unsigned u; memcpy(&u, &h, 4); return u;
}
__device__ __forceinline__ float bf_hi(float x) {
    return __bfloat162float(__float2bfloat16_rn(x));
}

__device__ __forceinline__ void mma_bf16(float* d, const unsigned* a,
                                         unsigned b0, unsigned b1) {
    asm volatile(
        "mma.sync.aligned.m16n8k16.row.col.f32.bf16.bf16.f32 "
        "{%0,%1,%2,%3}, {%4,%5,%6,%7}, {%8,%9}, {%0,%1,%2,%3};\n"
        : "+f"(d[0]), "+f"(d[1]), "+f"(d[2]), "+f"(d[3])
        : "r"(a[0]), "r"(a[1]), "r"(a[2]), "r"(a[3]), "r"(b0), "r"(b1));
}

// ---------------- init (+ fused dtype detection on block 0 / warp 0) ----------------
__global__ void v15_init(const int* ei32) {
    int i = blockIdx.x * blockDim.x + threadIdx.x;
    if (blockIdx.x == 0 && threadIdx.x < 32) {
        int lane = threadIdx.x;
        int acc = 0;
        for (int j = lane; j < 4096; j += 32) acc |= ei32[2 * j + 1];
#pragma unroll
        for (int o = 16; o > 0; o >>= 1) acc |= __shfl_down_sync(0xffffffffu, acc, o);
        if (lane == 0) v9_is64 = (acc == 0) ? 1 : 0;
    }
    int stride = gridDim.x * blockDim.x;
    for (int j = i; j < N_NODES * NUM_GRAPHS; j += stride) v14_C[j] = 0.f;
    if (i < N_NODES) v9_deg[i] = 1;               // self-loop pre-counted
    if (i < NUM_GRAPHS) v9_cnt[i] = 0;
}

__global__ void v9_count(const int* ei32, const int* batch32) {
    int i = blockIdx.x * blockDim.x + threadIdx.x;
    if (i < N_EDGES) {
        int dst = ld_idx(ei32, N_EDGES + i);
        atomicAdd(&v9_deg[dst], 1);
    }
    if (i < N_NODES) {
        int g = ld_idx(batch32, i);
        atomicAdd(&v9_cnt[g], 1);
    }
}

// fused: dinv + full exclusive scan -> rowptr/cursor. single block, 1024 threads.
__global__ void v15_scan() {
    __shared__ int ssum[1024];
    const int tid = threadIdx.x;
    const int C = (N_NODES + 1023) / 1024;   // 49
    int base = tid * C;
    int s = 0;
    for (int i = 0; i < C; i++) {
        int idx = base + i;
        if (idx < N_NODES) {
            int d = v9_deg[idx];
            s += d;
            v9_dinv[idx] = rsqrtf((float)d);
        }
    }
    ssum[tid] = s;
    __syncthreads();
    for (int off = 1; off < 1024; off <<= 1) {
        int v = (tid >= off) ? ssum[tid - off] : 0;
        __syncthreads();
        ssum[tid] += v;
        __syncthreads();
    }
    int run = (tid == 0) ? 0 : ssum[tid - 1];
    for (int i = 0; i < C; i++) {
        int idx = base + i;
        if (idx < N_NODES) {
            v9_rowptr[idx] = run;
            v9_cursor[idx] = run;
            run += v9_deg[idx];
        }
    }
    if (tid == 1023) v9_rowptr[N_NODES] = run;
}

__global__ void v9_fill(const int* ei32) {
    int i = blockIdx.x * blockDim.x + threadIdx.x;
    if (i < N_EDGES) {
        int src = ld_idx(ei32, i);
        int dst = ld_idx(ei32, N_EDGES + i);
        int pos = atomicAdd(&v9_cursor[dst], 1);
        v9_edge[pos] = make_int2(src, __float_as_int(v9_dinv[src]));
    } else if (i < TOT_ENTRIES) {
        int n = i - N_EDGES;
        int pos = atomicAdd(&v9_cursor[n], 1);
        v9_edge[pos] = make_int2(n, __float_as_int(v9_dinv[n]));
    }
}

// pooling coefficients C[s][g] = dinv[s] * sum_{(s->n) in E, n in g} dinv[n]
__global__ void v14_cbuild(const int* ei32, const int* batch32) {
    int i = blockIdx.x * blockDim.x + threadIdx.x;
    if (i < N_EDGES) {
        int s = ld_idx(ei32, i);
        int d = ld_idx(ei32, N_EDGES + i);
        int g = ld_idx(batch32, d);
        atomicAdd(&v14_C[s * NUM_GRAPHS + g], v9_dinv[s] * v9_dinv[d]);
    } else if (i < TOT_ENTRIES) {
        int n = i - N_EDGES;
        int g = ld_idx(batch32, n);
        float w = v9_dinv[n];
        atomicAdd(&v14_C[n * NUM_GRAPHS + g], w * w);
    }
}

// ---------------- tensor-core GEMM (split-bf16): v15_T(fp16) = src @ W ----------------
template<int SRC>
__global__ __launch_bounds__(256) void v15_gemm(const float* Xext, const float* W) {
    __shared__ unsigned Bs_hi[128][9];
    __shared__ unsigned Bs_lo[128][9];

    const float* X = (SRC == 0) ? Xext : (const float*)v9_hA;

    const int tid  = threadIdx.x;
    const int warp = tid >> 5;
    const int lane = tid & 31;
    const int gid  = lane >> 2;
    const int tig  = lane & 3;
    const int mw   = blockIdx.x * 128 + warp * 16;

    float acc[16][4];
#pragma unroll
    for (int nt = 0; nt < 16; nt++)
#pragma unroll
        for (int j = 0; j < 4; j++) acc[nt][j] = 0.f;

    const int r0 = mw + gid;
    const int r1 = mw + gid + 8;
    const bool vr0 = (r0 < N_NODES);
    const bool vr1 = (r1 < N_NODES);

    for (int kc = 0; kc < 8; kc++) {
        const int k0 = kc * 16;
#pragma unroll
        for (int i = 0; i < 4; i++) {
            int p  = tid + i * 256;
            int n  = p & 127;
            int k2 = p >> 7;
            float w0 = W[(k0 + 2 * k2) * 128 + n];
            float w1 = W[(k0 + 2 * k2 + 1) * 128 + n];
            float h0 = bf_hi(w0), h1 = bf_hi(w1);
            Bs_hi[n][k2] = pk_bf2(h0, h1);
            Bs_lo[n][k2] = pk_bf2(w0 - h0, w1 - h1);
        }
        __syncthreads();

        float2 x00 = make_float2(0.f, 0.f), x01 = x00, x10 = x00, x11 = x00;
        if (vr0) {
            x00 = *(const float2*)&X[r0 * 128 + k0 + tig * 2];
            x01 = *(const float2*)&X[r0 * 128 + k0 + tig * 2 + 8];
        }
        if (vr1) {
            x10 = *(const float2*)&X[r1 * 128 + k0 + tig * 2];
            x11 = *(const float2*)&X[r1 * 128 + k0 + tig * 2 + 8];
        }
        unsigned a_hi[4], a_lo[4];
        {
            float hx, hy;
            hx = bf_hi(x00.x); hy = bf_hi(x00.y);
            a_hi[0] = pk_bf2(hx, hy); a_lo[0] = pk_bf2(x00.x - hx, x00.y - hy);
            hx = bf_hi(x10.x); hy = bf_hi(x10.y);
            a_hi[1] = pk_bf2(hx, hy); a_lo[1] = pk_bf2(x10.x - hx, x10.y - hy);
            hx = bf_hi(x01.x); hy = bf_hi(x01.y);
            a_hi[2] = pk_bf2(hx, hy); a_lo[2] = pk_bf2(x01.x - hx, x01.y - hy);
            hx = bf_hi(x11.x); hy = bf_hi(x11.y);
            a_hi[3] = pk_bf2(hx, hy); a_lo[3] = pk_bf2(x11.x - hx, x11.y - hy);
        }

#pragma unroll
        for (int nt = 0; nt < 16; nt++) {
            int n = nt * 8 + gid;
            unsigned bh0 = Bs_hi[n][tig];
            unsigned bh1 = Bs_hi[n][tig + 4];
            unsigned bl0 = Bs_lo[n][tig];
            unsigned bl1 = Bs_lo[n][tig + 4];
            mma_bf16(acc[nt], a_hi, bh0, bh1);
            mma_bf16(acc[nt], a_hi, bl0, bl1);
            mma_bf16(acc[nt], a_lo, bh0, bh1);
        }
        __syncthreads();
    }

    // epilogue -> fp16 T
#pragma unroll
    for (int nt = 0; nt < 16; nt++) {
        int n = nt * 8 + tig * 2;
        if (vr0) *(__half2*)&v15_T[r0 * 128 + n] = __floats2half2_rn(acc[nt][0], acc[nt][1]);
        if (vr1) *(__half2*)&v15_T[r1 * 128 + n] = __floats2half2_rn(acc[nt][2], acc[nt][3]);
    }
}

// ---------------- aggregation: one warp per node, fp16 uint2 gathers ----------------
// DST: 1 -> v9_hA, 2 -> v9_hB ; reads v15_T
template<int DST>
__global__ __launch_bounds__(256) void v15_agg(const float* bias) {
    int node = (blockIdx.x * blockDim.x + threadIdx.x) >> 5;
    int lane = threadIdx.x & 31;
    if (node >= N_NODES) return;

    int beg = v9_rowptr[node];
    int end = v9_rowptr[node + 1];

    float ax = 0.f, ay = 0.f, az = 0.f, aw = 0.f;
    int e = beg;
    for (; e + 1 < end; e += 2) {
        int2 e0 = v9_edge[e];
        int2 e1 = v9_edge[e + 1];
        float w0 = __int_as_float(e0.y);
        float w1 = __int_as_float(e1.y);
        uint2 u0 = *(const uint2*)&v15_T[e0.x * 128 + lane * 4];
        uint2 u1 = *(const uint2*)&v15_T[e1.x * 128 + lane * 4];
        float2 f00 = __half22float2(*(__half2*)&u0.x);
        float2 f01 = __half22float2(*(__half2*)&u0.y);
        float2 f10 = __half22float2(*(__half2*)&u1.x);
        float2 f11 = __half22float2(*(__half2*)&u1.y);
        ax = fmaf(w0, f00.x, ax); ay = fmaf(w0, f00.y, ay);
        az = fmaf(w0, f01.x, az); aw = fmaf(w0, f01.y, aw);
        ax = fmaf(w1, f10.x, ax); ay = fmaf(w1, f10.y, ay);
        az = fmaf(w1, f11.x, az); aw = fmaf(w1, f11.y, aw);
    }
    if (e < end) {
        int2 e0 = v9_edge[e];
        float w = __int_as_float(e0.y);
        uint2 u0 = *(const uint2*)&v15_T[e0.x * 128 + lane * 4];
        float2 f00 = __half22float2(*(__half2*)&u0.x);
        float2 f01 = __half22float2(*(__half2*)&u0.y);
        ax = fmaf(w, f00.x, ax); ay = fmaf(w, f00.y, ay);
        az = fmaf(w, f01.x, az); aw = fmaf(w, f01.y, aw);
    }
    float dn = v9_dinv[node];
    float4 b = *(const float4*)&bias[lane * 4];
    float4 o;
    o.x = fmaxf(fmaf(ax, dn, b.x), 0.f);
    o.y = fmaxf(fmaf(ay, dn, b.y), 0.f);
    o.z = fmaxf(fmaf(az, dn, b.z), 0.f);
    o.w = fmaxf(fmaf(aw, dn, b.w), 0.f);
    float* Out = (DST == 1) ? v9_hA : v9_hB;
    *(float4*)&Out[node * 128 + lane * 4] = o;
}

// ---------------- pooled GEMM: partial[b] = C[s-range]^T @ h2[s-range] ----------------
__global__ __launch_bounds__(256) void v14_cgemm() {
    __shared__ float Cs[16][65];
    __shared__ float Hs[16][132];

    const int b  = blockIdx.x;
    const int s0 = b * CK;
    const int s1 = (s0 + CK < N_NODES) ? s0 + CK : N_NODES;
    const int tid = threadIdx.x;
    const int ty  = tid >> 4;
    const int tx  = tid & 15;

    float acc[4][8];
#pragma unroll
    for (int r = 0; r < 4; r++)
#pragma unroll
        for (int c = 0; c < 8; c++) acc[r][c] = 0.f;

    for (int c0 = s0; c0 < s1; c0 += 16) {
#pragma unroll
        for (int i = 0; i < 4; i++) {
            int p = tid + i * 256;
            int k = p >> 6, g = p & 63;
            int s = c0 + k;
            Cs[k][g] = (s < s1) ? v14_C[s * NUM_GRAPHS + g] : 0.f;
        }
#pragma unroll
        for (int i = 0; i < 2; i++) {
            int p = tid + i * 256;
            int k = p >> 5, q = p & 31;
            int s = c0 + k;
            float4 v = (s < s1) ? *(const float4*)&v9_hB[s * 128 + q * 4]
                                : make_float4(0.f, 0.f, 0.f, 0.f);
            *(float4*)&Hs[k][q * 4] = v;
        }
        __syncthreads();
#pragma unroll
        for (int k = 0; k < 16; k++) {
            float a4[4];
#pragma unroll
            for (int r = 0; r < 4; r++) a4[r] = Cs[k][ty * 4 + r];
            float b8[8];
#pragma unroll
            for (int c = 0; c < 8; c++) b8[c] = Hs[k][tx * 8 + c];
#pragma unroll
            for (int r = 0; r < 4; r++)
#pragma unroll
                for (int c = 0; c < 8; c++)
                    acc[r][c] = fmaf(a4[r], b8[c], acc[r][c]);
        }
        __syncthreads();
    }
#pragma unroll
    for (int r = 0; r < 4; r++) {
        int g = ty * 4 + r;
        *(float4*)&v14_partial[b * 8192 + g * 128 + tx * 8]     =
            make_float4(acc[r][0], acc[r][1], acc[r][2], acc[r][3]);
        *(float4*)&v14_partial[b * 8192 + g * 128 + tx * 8 + 4] =
            make_float4(acc[r][4], acc[r][5], acc[r][6], acc[r][7]);
    }
}

// reduce partials -> mean -> @W3 + b3
__global__ void v14_wfold(const float* W3, const float* b3) {
    __shared__ float Ps[128];
    int g = blockIdx.x, c = threadIdx.x;
    float p = 0.f;
#pragma unroll 8
    for (int b = 0; b < CSPLIT; b++) p += v14_partial[b * 8192 + g * 128 + c];
    float invc = 1.f / fmaxf((float)v9_cnt[g], 1.f);
    Ps[c] = p * invc;
    __syncthreads();
    float s = b3[c];
#pragma unroll 8
    for (int k = 0; k < 128; k++)
        s = fmaf(Ps[k], W3[k * 128 + c], s);
    v9_pooled2[g * 128 + c] = s;
}

// ---------------- classifier MLP ----------------
__global__ void v12_mlp1(const float* C1, const float* bc1) {
    int idx = blockIdx.x * blockDim.x + threadIdx.x;
    if (idx >= NUM_GRAPHS * DIM) return;
    int g = idx >> 7, c = idx & 127;
    float s = bc1[c];
#pragma unroll 8
    for (int k = 0; k < 128; k++)
        s = fmaf(v9_pooled2[g * 128 + k], C1[k * 128 + c], s);
    v9_hid[idx] = fmaxf(s, 0.f);
}

__global__ void v9_mlp2(const float* C2, const float* bc2, float* out) {
    int idx = threadIdx.x;
    if (idx >= NUM_GRAPHS * NUM_CLASSES) return;
    int g = idx / NUM_CLASSES, c = idx % NUM_CLASSES;
    float s = bc2[c];
#pragma unroll 8
    for (int k = 0; k < 128; k++)
        s = fmaf(v9_hid[g * 128 + k], C2[k * NUM_CLASSES + c], s);
    out[idx] = s;
}

// ---------------- launch ----------------
extern "C" void kernel_launch(void* const* d_in, const int* in_sizes, int n_in,
                              void* d_out, int out_size) {
    const float* x       = (const float*)d_in[0];
    const int*   ei32    = (const int*)d_in[1];
    const int*   batch32 = (const int*)d_in[2];
    const float* W1 = (const float*)d_in[3];  const float* b1 = (const float*)d_in[4];
    const float* W2 = (const float*)d_in[5];  const float* b2 = (const float*)d_in[6];
    const float* W3 = (const float*)d_in[7];  const float* b3 = (const float*)d_in[8];
    const float* C1 = (const float*)d_in[9];  const float* bc1 = (const float*)d_in[10];
    const float* C2 = (const float*)d_in[11]; const float* bc2 = (const float*)d_in[12];
    float* out = (float*)d_out;

    const int TPB = 256;
    const int GEMM_BLOCKS = (N_NODES + 127) / 128;
    const int AGG_BLOCKS  = (N_NODES * 32 + TPB - 1) / TPB;

    cudaStream_t s2;
    cudaStreamCreateWithFlags(&s2, cudaStreamNonBlocking);
    cudaEvent_t evF, evJ1, evJ2;
    cudaEventCreateWithFlags(&evF,  cudaEventDisableTiming);
    cudaEventCreateWithFlags(&evJ1, cudaEventDisableTiming);
    cudaEventCreateWithFlags(&evJ2, cudaEventDisableTiming);

    cudaEventRecord(evF, 0);
    cudaStreamWaitEvent(s2, evF, 0);

    v15_init  <<<(N_NODES + TPB - 1) / TPB, TPB, 0, s2>>>(ei32);
    v9_count  <<<(N_EDGES + TPB - 1) / TPB, TPB, 0, s2>>>(ei32, batch32);
    v15_scan  <<<1, 1024, 0, s2>>>();
    v9_fill   <<<(TOT_ENTRIES + TPB - 1) / TPB, TPB, 0, s2>>>(ei32);
    cudaEventRecord(evJ1, s2);
    v14_cbuild<<<(TOT_ENTRIES + TPB - 1) / TPB, TPB, 0, s2>>>(ei32, batch32);
    cudaEventRecord(evJ2, s2);

    // layer-1 GEMM overlaps the preprocessing
    v15_gemm<0><<<GEMM_BLOCKS, TPB>>>(x, W1);

    cudaStreamWaitEvent(0, evJ1, 0);

    // layer 1: aggregate T -> hA (relu, +b1)
    v15_agg<1><<<AGG_BLOCKS, TPB>>>(b1);
    // layer 2: hA @ W2 -> T ; aggregate -> hB (relu, +b2)
    v15_gemm<1><<<GEMM_BLOCKS, TPB>>>(x, W2);
    v15_agg<2><<<AGG_BLOCKS, TPB>>>(b2);

    // folded layer 3 + pooling: pooled = C^T @ hB (split-k), then mean + @W3 + b3
    cudaStreamWaitEvent(0, evJ2, 0);
    v14_cgemm<<<CSPLIT, TPB>>>();
    v14_wfold<<<NUM_GRAPHS, 128>>>(W3, b3);

    // classifier
    v12_mlp1<<<(NUM_GRAPHS * DIM + TPB - 1) / TPB, TPB>>>(C1, bc1);
    v9_mlp2<<<1, 256>>>(C2, bc2, out);
}

// round 16
// speedup vs baseline: 1.3204x; 1.3204x over previous
#include <cuda_runtime.h>
#include <cuda_bf16.h>
#include <cuda_fp16.h>
#include <cstring>

#define N_NODES   50000
#define N_EDGES   800000
#define DIM       128
#define NUM_GRAPHS 64
#define NUM_CLASSES 3
#define TOT_ENTRIES (N_EDGES + N_NODES)
#define NSEG ((N_NODES + 127) / 128)       // 391
#define CSPLIT 64
#define CK ((N_NODES + CSPLIT - 1) / CSPLIT)   // 782

// ---------------- scratch (device globals; sanctioned, no allocation) ----------------
__device__ int   v9_is64;
__device__ int   v9_deg[N_NODES];
__device__ float v9_dinv[N_NODES];
__device__ int   v9_segsum[NSEG];
__device__ int   v9_segoff[NSEG];
__device__ int   v9_rowptr[N_NODES + 1];
__device__ int   v9_cursor[N_NODES];
__device__ __align__(8)  int2  v9_edge[TOT_ENTRIES];   // (src, dinv[src] bits)
__device__ __align__(16) __half v15_T[N_NODES * DIM];  // fp16 gathered buffer
__device__ __align__(16) float v9_hA[N_NODES * DIM];
__device__ __align__(16) float v9_hB[N_NODES * DIM];
__device__ __align__(16) float v14_C[N_NODES * NUM_GRAPHS];        // c[s][g]
__device__ __align__(16) float v14_partial[CSPLIT * NUM_GRAPHS * DIM];
__device__ __align__(16) float v9_pooled2[NUM_GRAPHS * DIM];       // mean(z)*W3 + b3
__device__ int   v9_cnt[NUM_GRAPHS];
__device__ __align__(16) float v9_hid[NUM_GRAPHS * DIM];

__device__ __forceinline__ int ld_idx(const int* p, int i) {
    return v9_is64 ? p[2 * i] : p[i];
}

__device__ __forceinline__ int v9_incl_scan(int v, int lane) {
#pragma unroll
    for (int o = 1; o < 32; o <<= 1) {
        int n = __shfl_up_sync(0xffffffffu, v, o);
        if (lane >= o) v += n;
    }
    return v;
}

__device__ __forceinline__ unsigned pk_bf2(float x, float y) {
    __nv_bfloat162 h = __floats2bfloat162_rn(x, y);
    unsigned u; memcpy(&u, &h, 4); return u;
}
__device__ __forceinline__ float bf_hi(float x) {
    return __bfloat162float(__float2bfloat16_rn(x));
}

__device__ __forceinline__ void mma_bf16(float* d, const unsigned* a,
                                         unsigned b0, unsigned b1) {
    asm volatile(
        "mma.sync.aligned.m16n8k16.row.col.f32.bf16.bf16.f32 "
        "{%0,%1,%2,%3}, {%4,%5,%6,%7}, {%8,%9}, {%0,%1,%2,%3};\n"
        : "+f"(d[0]), "+f"(d[1]), "+f"(d[2]), "+f"(d[3])
        : "r"(a[0]), "r"(a[1]), "r"(a[2]), "r"(a[3]), "r"(b0), "r"(b1));
}

// ---------------- init (deg/cnt + fused dtype detection; NO C-zeroing here) ----------------
__global__ void v16_init(const int* ei32) {
    int i = blockIdx.x * blockDim.x + threadIdx.x;
    if (blockIdx.x == 0 && threadIdx.x < 32) {
        int lane = threadIdx.x;
        int acc = 0;
        for (int j = lane; j < 4096; j += 32) acc |= ei32[2 * j + 1];
#pragma unroll
        for (int o = 16; o > 0; o >>= 1) acc |= __shfl_down_sync(0xffffffffu, acc, o);
        if (lane == 0) v9_is64 = (acc == 0) ? 1 : 0;
    }
    if (i < N_NODES) v9_deg[i] = 1;               // self-loop pre-counted
    if (i < NUM_GRAPHS) v9_cnt[i] = 0;
}

__global__ void v9_count(const int* ei32, const int* batch32) {
    int i = blockIdx.x * blockDim.x + threadIdx.x;
    if (i < N_EDGES) {
        int dst = ld_idx(ei32, N_EDGES + i);
        atomicAdd(&v9_deg[dst], 1);
    }
    if (i < N_NODES) {
        int g = ld_idx(batch32, i);
        atomicAdd(&v9_cnt[g], 1);
    }
}

// stage 1: per-segment degree sums + fused dinv computation
__global__ void v16_segsum_k() {
    int w    = (blockIdx.x * blockDim.x + threadIdx.x) >> 5;
    int lane = threadIdx.x & 31;
    if (w >= NSEG) return;
    int s = 0;
#pragma unroll
    for (int c = 0; c < 4; c++) {
        int i = w * 128 + c * 32 + lane;
        if (i < N_NODES) {
            int d = v9_deg[i];
            s += d;
            v9_dinv[i] = rsqrtf((float)d);
        }
    }
#pragma unroll
    for (int o = 16; o > 0; o >>= 1) s += __shfl_down_sync(0xffffffffu, s, o);
    if (lane == 0) v9_segsum[w] = s;
}

// stage 2: exclusive scan over segment sums, single warp
__global__ void v9_segscan_k() {
    int lane = threadIdx.x;
    int carry = 0;
    for (int base = 0; base < NSEG; base += 32) {
        int i = base + lane;
        int v = (i < NSEG) ? v9_segsum[i] : 0;
        int s = v9_incl_scan(v, lane);
        if (i < NSEG) v9_segoff[i] = carry + s - v;
        carry += __shfl_sync(0xffffffffu, s, 31);
    }
}

// stage 3: per-segment node-level exclusive scan -> rowptr/cursor
__global__ void v9_rowptr_k() {
    int w    = (blockIdx.x * blockDim.x + threadIdx.x) >> 5;
    int lane = threadIdx.x & 31;
    if (w >= NSEG) return;
    int carry = v9_segoff[w];
#pragma unroll
    for (int c = 0; c < 4; c++) {
        int i = w * 128 + c * 32 + lane;
        int v = (i < N_NODES) ? v9_deg[i] : 0;
        int s = v9_incl_scan(v, lane);
        if (i < N_NODES) {
            int ex = carry + s - v;
            v9_rowptr[i] = ex;
            v9_cursor[i] = ex;
        }
        carry += __shfl_sync(0xffffffffu, s, 31);
    }
    if (w == NSEG - 1 && lane == 0) v9_rowptr[N_NODES] = carry;
}

__global__ void v9_fill(const int* ei32) {
    int i = blockIdx.x * blockDim.x + threadIdx.x;
    if (i < N_EDGES) {
        int src = ld_idx(ei32, i);
        int dst = ld_idx(ei32, N_EDGES + i);
        int pos = atomicAdd(&v9_cursor[dst], 1);
        v9_edge[pos] = make_int2(src, __float_as_int(v9_dinv[src]));
    } else if (i < TOT_ENTRIES) {
        int n = i - N_EDGES;
        int pos = atomicAdd(&v9_cursor[n], 1);
        v9_edge[pos] = make_int2(n, __float_as_int(v9_dinv[n]));
    }
}

// zero pooling coefficient matrix (off the agg1-gating path)
__global__ void v16_zeroC() {
    int i = blockIdx.x * blockDim.x + threadIdx.x;
    int stride = gridDim.x * blockDim.x;
    for (int j = i; j < N_NODES * NUM_GRAPHS / 4; j += stride)
        *(float4*)&v14_C[j * 4] = make_float4(0.f, 0.f, 0.f, 0.f);
}

// pooling coefficients C[s][g] = dinv[s] * sum_{(s->n) in E, n in g} dinv[n]
__global__ void v14_cbuild(const int* ei32, const int* batch32) {
    int i = blockIdx.x * blockDim.x + threadIdx.x;
    if (i < N_EDGES) {
        int s = ld_idx(ei32, i);
        int d = ld_idx(ei32, N_EDGES + i);
        int g = ld_idx(batch32, d);
        atomicAdd(&v14_C[s * NUM_GRAPHS + g], v9_dinv[s] * v9_dinv[d]);
    } else if (i < TOT_ENTRIES) {
        int n = i - N_EDGES;
        int g = ld_idx(batch32, n);
        float w = v9_dinv[n];
        atomicAdd(&v14_C[n * NUM_GRAPHS + g], w * w);
    }
}

// ---------------- tensor-core GEMM (split-bf16): v15_T(fp16) = src @ W ----------------
template<int SRC>
__global__ __launch_bounds__(256) void v15_gemm(const float* Xext, const float* W) {
    __shared__ unsigned Bs_hi[128][9];
    __shared__ unsigned Bs_lo[128][9];

    const float* X = (SRC == 0) ? Xext : (const float*)v9_hA;

    const int tid  = threadIdx.x;
    const int warp = tid >> 5;
    const int lane = tid & 31;
    const int gid  = lane >> 2;
    const int tig  = lane & 3;
    const int mw   = blockIdx.x * 128 + warp * 16;

    float acc[16][4];
#pragma unroll
    for (int nt = 0; nt < 16; nt++)
#pragma unroll
        for (int j = 0; j < 4; j++) acc[nt][j] = 0.f;

    const int r0 = mw + gid;
    const int r1 = mw + gid + 8;
    const bool vr0 = (r0 < N_NODES);
    const bool vr1 = (r1 < N_NODES);

    for (int kc = 0; kc < 8; kc++) {
        const int k0 = kc * 16;
#pragma unroll
        for (int i = 0; i < 4; i++) {
            int p  = tid + i * 256;
            int n  = p & 127;
            int k2 = p >> 7;
            float w0 = W[(k0 + 2 * k2) * 128 + n];
            float w1 = W[(k0 + 2 * k2 + 1) * 128 + n];
            float h0 = bf_hi(w0), h1 = bf_hi(w1);
            Bs_hi[n][k2] = pk_bf2(h0, h1);
            Bs_lo[n][k2] = pk_bf2(w0 - h0, w1 - h1);
        }
        __syncthreads();

        float2 x00 = make_float2(0.f, 0.f), x01 = x00, x10 = x00, x11 = x00;
        if (vr0) {
            x00 = *(const float2*)&X[r0 * 128 + k0 + tig * 2];
            x01 = *(const float2*)&X[r0 * 128 + k0 + tig * 2 + 8];
        }
        if (vr1) {
            x10 = *(const float2*)&X[r1 * 128 + k0 + tig * 2];
            x11 = *(const float2*)&X[r1 * 128 + k0 + tig * 2 + 8];
        }
        unsigned a_hi[4], a_lo[4];
        {
            float hx, hy;
            hx = bf_hi(x00.x); hy = bf_hi(x00.y);
            a_hi[0] = pk_bf2(hx, hy); a_lo[0] = pk_bf2(x00.x - hx, x00.y - hy);
            hx = bf_hi(x10.x); hy = bf_hi(x10.y);
            a_hi[1] = pk_bf2(hx, hy); a_lo[1] = pk_bf2(x10.x - hx, x10.y - hy);
            hx = bf_hi(x01.x); hy = bf_hi(x01.y);
            a_hi[2] = pk_bf2(hx, hy); a_lo[2] = pk_bf2(x01.x - hx, x01.y - hy);
            hx = bf_hi(x11.x); hy = bf_hi(x11.y);
            a_hi[3] = pk_bf2(hx, hy); a_lo[3] = pk_bf2(x11.x - hx, x11.y - hy);
        }

#pragma unroll
        for (int nt = 0; nt < 16; nt++) {
            int n = nt * 8 + gid;
            unsigned bh0 = Bs_hi[n][tig];
            unsigned bh1 = Bs_hi[n][tig + 4];
            unsigned bl0 = Bs_lo[n][tig];
            unsigned bl1 = Bs_lo[n][tig + 4];
            mma_bf16(acc[nt], a_hi, bh0, bh1);
            mma_bf16(acc[nt], a_hi, bl0, bl1);
            mma_bf16(acc[nt], a_lo, bh0, bh1);
        }
        __syncthreads();
    }

    // epilogue -> fp16 T
#pragma unroll
    for (int nt = 0; nt < 16; nt++) {
        int n = nt * 8 + tig * 2;
        if (vr0) *(__half2*)&v15_T[r0 * 128 + n] = __floats2half2_rn(acc[nt][0], acc[nt][1]);
        if (vr1) *(__half2*)&v15_T[r1 * 128 + n] = __floats2half2_rn(acc[nt][2], acc[nt][3]);
    }
}

// ---------------- aggregation: one warp per node, fp16 uint2 gathers ----------------
// DST: 1 -> v9_hA, 2 -> v9_hB ; reads v15_T
template<int DST>
__global__ __launch_bounds__(256) void v15_agg(const float* bias) {
    int node = (blockIdx.x * blockDim.x + threadIdx.x) >> 5;
    int lane = threadIdx.x & 31;
    if (node >= N_NODES) return;

    int beg = v9_rowptr[node];
    int end = v9_rowptr[node + 1];

    float ax = 0.f, ay = 0.f, az = 0.f, aw = 0.f;
    int e = beg;
    for (; e + 1 < end; e += 2) {
        int2 e0 = v9_edge[e];
        int2 e1 = v9_edge[e + 1];
        float w0 = __int_as_float(e0.y);
        float w1 = __int_as_float(e1.y);
        uint2 u0 = *(const uint2*)&v15_T[e0.x * 128 + lane * 4];
        uint2 u1 = *(const uint2*)&v15_T[e1.x * 128 + lane * 4];
        float2 f00 = __half22float2(*(__half2*)&u0.x);
        float2 f01 = __half22float2(*(__half2*)&u0.y);
        float2 f10 = __half22float2(*(__half2*)&u1.x);
        float2 f11 = __half22float2(*(__half2*)&u1.y);
        ax = fmaf(w0, f00.x, ax); ay = fmaf(w0, f00.y, ay);
        az = fmaf(w0, f01.x, az); aw = fmaf(w0, f01.y, aw);
        ax = fmaf(w1, f10.x, ax); ay = fmaf(w1, f10.y, ay);
        az = fmaf(w1, f11.x, az); aw = fmaf(w1, f11.y, aw);
    }
    if (e < end) {
        int2 e0 = v9_edge[e];
        float w = __int_as_float(e0.y);
        uint2 u0 = *(const uint2*)&v15_T[e0.x * 128 + lane * 4];
        float2 f00 = __half22float2(*(__half2*)&u0.x);
        float2 f01 = __half22float2(*(__half2*)&u0.y);
        ax = fmaf(w, f00.x, ax); ay = fmaf(w, f00.y, ay);
        az = fmaf(w, f01.x, az); aw = fmaf(w, f01.y, aw);
    }
    float dn = v9_dinv[node];
    float4 b = *(const float4*)&bias[lane * 4];
    float4 o;
    o.x = fmaxf(fmaf(ax, dn, b.x), 0.f);
    o.y = fmaxf(fmaf(ay, dn, b.y), 0.f);
    o.z = fmaxf(fmaf(az, dn, b.z), 0.f);
    o.w = fmaxf(fmaf(aw, dn, b.w), 0.f);
    float* Out = (DST == 1) ? v9_hA : v9_hB;
    *(float4*)&Out[node * 128 + lane * 4] = o;
}

// ---------------- pooled GEMM: partial[b] = C[s-range]^T @ h2[s-range] ----------------
__global__ __launch_bounds__(256) void v14_cgemm() {
    __shared__ float Cs[16][65];
    __shared__ float Hs[16][132];

    const int b  = blockIdx.x;
    const int s0 = b * CK;
    const int s1 = (s0 + CK < N_NODES) ? s0 + CK : N_NODES;
    const int tid = threadIdx.x;
    const int ty  = tid >> 4;
    const int tx  = tid & 15;

    float acc[4][8];
#pragma unroll
    for (int r = 0; r < 4; r++)
#pragma unroll
        for (int c = 0; c < 8; c++) acc[r][c] = 0.f;

    for (int c0 = s0; c0 < s1; c0 += 16) {
#pragma unroll
        for (int i = 0; i < 4; i++) {
            int p = tid + i * 256;
            int k = p >> 6, g = p & 63;
            int s = c0 + k;
            Cs[k][g] = (s < s1) ? v14_C[s * NUM_GRAPHS + g] : 0.f;
        }
#pragma unroll
        for (int i = 0; i < 2; i++) {
            int p = tid + i * 256;
            int k = p >> 5, q = p & 31;
            int s = c0 + k;
            float4 v = (s < s1) ? *(const float4*)&v9_hB[s * 128 + q * 4]
                                : make_float4(0.f, 0.f, 0.f, 0.f);
            *(float4*)&Hs[k][q * 4] = v;
        }
        __syncthreads();
#pragma unroll
        for (int k = 0; k < 16; k++) {
            float a4[4];
#pragma unroll
            for (int r = 0; r < 4; r++) a4[r] = Cs[k][ty * 4 + r];
            float b8[8];
#pragma unroll
            for (int c = 0; c < 8; c++) b8[c] = Hs[k][tx * 8 + c];
#pragma unroll
            for (int r = 0; r < 4; r++)
#pragma unroll
                for (int c = 0; c < 8; c++)
                    acc[r][c] = fmaf(a4[r], b8[c], acc[r][c]);
        }
        __syncthreads();
    }
#pragma unroll
    for (int r = 0; r < 4; r++) {
        int g = ty * 4 + r;
        *(float4*)&v14_partial[b * 8192 + g * 128 + tx * 8]     =
            make_float4(acc[r][0], acc[r][1], acc[r][2], acc[r][3]);
        *(float4*)&v14_partial[b * 8192 + g * 128 + tx * 8 + 4] =
            make_float4(acc[r][4], acc[r][5], acc[r][6], acc[r][7]);
    }
}

// reduce partials -> mean -> @W3 + b3
__global__ void v14_wfold(const float* W3, const float* b3) {
    __shared__ float Ps[128];
    int g = blockIdx.x, c = threadIdx.x;
    float p = 0.f;
#pragma unroll 8
    for (int b = 0; b < CSPLIT; b++) p += v14_partial[b * 8192 + g * 128 + c];
    float invc = 1.f / fmaxf((float)v9_cnt[g], 1.f);
    Ps[c] = p * invc;
    __syncthreads();
    float s = b3[c];
#pragma unroll 8
    for (int k = 0; k < 128; k++)
        s = fmaf(Ps[k], W3[k * 128 + c], s);
    v9_pooled2[g * 128 + c] = s;
}

// ---------------- classifier MLP ----------------
__global__ void v12_mlp1(const float* C1, const float* bc1) {
    int idx = blockIdx.x * blockDim.x + threadIdx.x;
    if (idx >= NUM_GRAPHS * DIM) return;
    int g = idx >> 7, c = idx & 127;
    float s = bc1[c];
#pragma unroll 8
    for (int k = 0; k < 128; k++)
        s = fmaf(v9_pooled2[g * 128 + k], C1[k * 128 + c], s);
    v9_hid[idx] = fmaxf(s, 0.f);
}

__global__ void v9_mlp2(const float* C2, const float* bc2, float* out) {
    int idx = threadIdx.x;
    if (idx >= NUM_GRAPHS * NUM_CLASSES) return;
    int g = idx / NUM_CLASSES, c = idx % NUM_CLASSES;
    float s = bc2[c];
#pragma unroll 8
    for (int k = 0; k < 128; k++)
        s = fmaf(v9_hid[g * 128 + k], C2[k * NUM_CLASSES + c], s);
    out[idx] = s;
}

// ---------------- launch ----------------
extern "C" void kernel_launch(void* const* d_in, const int* in_sizes, int n_in,
                              void* d_out, int out_size) {
    const float* x       = (const float*)d_in[0];
    const int*   ei32    = (const int*)d_in[1];
    const int*   batch32 = (const int*)d_in[2];
    const float* W1 = (const float*)d_in[3];  const float* b1 = (const float*)d_in[4];
    const float* W2 = (const float*)d_in[5];  const float* b2 = (const float*)d_in[6];
    const float* W3 = (const float*)d_in[7];  const float* b3 = (const float*)d_in[8];
    const float* C1 = (const float*)d_in[9];  const float* bc1 = (const float*)d_in[10];
    const float* C2 = (const float*)d_in[11]; const float* bc2 = (const float*)d_in[12];
    float* out = (float*)d_out;

    const int TPB = 256;
    const int SEG_BLOCKS  = (NSEG * 32 + TPB - 1) / TPB;
    const int GEMM_BLOCKS = (N_NODES + 127) / 128;
    const int AGG_BLOCKS  = (N_NODES * 32 + TPB - 1) / TPB;

    cudaStream_t s2;
    cudaStreamCreateWithFlags(&s2, cudaStreamNonBlocking);
    cudaEvent_t evF, evJ1, evJ2;
    cudaEventCreateWithFlags(&evF,  cudaEventDisableTiming);
    cudaEventCreateWithFlags(&evJ1, cudaEventDisableTiming);
    cudaEventCreateWithFlags(&evJ2, cudaEventDisableTiming);

    cudaEventRecord(evF, 0);
    cudaStreamWaitEvent(s2, evF, 0);

    v16_init    <<<(N_NODES + TPB - 1) / TPB, TPB, 0, s2>>>(ei32);
    v9_count    <<<(N_EDGES + TPB - 1) / TPB, TPB, 0, s2>>>(ei32, batch32);
    v16_segsum_k<<<SEG_BLOCKS, TPB, 0, s2>>>();
    v9_segscan_k<<<1, 32, 0, s2>>>();
    v9_rowptr_k <<<SEG_BLOCKS, TPB, 0, s2>>>();
    v9_fill     <<<(TOT_ENTRIES + TPB - 1) / TPB, TPB, 0, s2>>>(ei32);
    cudaEventRecord(evJ1, s2);
    v16_zeroC   <<<256, TPB, 0, s2>>>();
    v14_cbuild  <<<(TOT_ENTRIES + TPB - 1) / TPB, TPB, 0, s2>>>(ei32, batch32);
    cudaEventRecord(evJ2, s2);

    // layer-1 GEMM overlaps the preprocessing
    v15_gemm<0><<<GEMM_BLOCKS, TPB>>>(x, W1);

    cudaStreamWaitEvent(0, evJ1, 0);

    // layer 1: aggregate T -> hA (relu, +b1)
    v15_agg<1><<<AGG_BLOCKS, TPB>>>(b1);
    // layer 2: hA @ W2 -> T ; aggregate -> hB (relu, +b2)
    v15_gemm<1><<<GEMM_BLOCKS, TPB>>>(x, W2);
    v15_agg<2><<<AGG_BLOCKS, TPB>>>(b2);

    // folded layer 3 + pooling: pooled = C^T @ hB (split-k), then mean + @W3 + b3
    cudaStreamWaitEvent(0, evJ2, 0);
    v14_cgemm<<<CSPLIT, TPB>>>();
    v14_wfold<<<NUM_GRAPHS, 128>>>(W3, b3);

    // classifier
    v12_mlp1<<<(NUM_GRAPHS * DIM + TPB - 1) / TPB, TPB>>>(C1, bc1);
    v9_mlp2<<<1, 256>>>(C2, bc2, out);
}